// round 1
// baseline (speedup 1.0000x reference)
#include <cuda_runtime.h>

// AdditiveAttention: B=4, Q=512, K=512, H=256, E=256, DV=256
//   q = queries @ W_q^T            [B,Q,H]
//   k = keys    @ W_k^T            [B,K,H]
//   s[b,q,k] = sum_h w_v[h] * tanh(q[b,q,h] + k[b,k,h])
//   attn = softmax_k(s);  out = attn @ values   [B,Q,DV]

#define BB 4
#define QQ 512
#define KK 512
#define HH 256
#define EE 256
#define DVV 256

// scratch (device globals: no allocations allowed)
__device__ float4 g_qv[BB * QQ * HH / 4];   // 2 MB
__device__ float4 g_kv[BB * KK * HH / 4];   // 2 MB
__device__ float4 g_sv[BB * QQ * KK / 4];   // 4 MB

__device__ __forceinline__ float tanh_fast(float x) {
    float y;
    asm("tanh.approx.f32 %0, %1;" : "=f"(y) : "f"(x));
    return y;
}

// ---------------------------------------------------------------------------
// Projection GEMM: C[r][h] = sum_e A[r][e] * W[h][e]
// A: [2048, 256] row-major, W: [256, 256] row-major ([out,in]).
// 64x64 tile per block, 256 threads, 4x4 register tile per thread.
// blockIdx.z selects (queries,W_q)->g_q or (keys,W_k)->g_k.
// ---------------------------------------------------------------------------
__global__ __launch_bounds__(256) void proj_kernel(
    const float* __restrict__ Aq, const float* __restrict__ Wq,
    const float* __restrict__ Ak, const float* __restrict__ Wk)
{
    const float* A; const float* W; float* C;
    if (blockIdx.z == 0) { A = Aq; W = Wq; C = (float*)g_qv; }
    else                 { A = Ak; W = Wk; C = (float*)g_kv; }

    const int row0 = blockIdx.x * 64;   // 0..31 -> rows
    const int col0 = blockIdx.y * 64;   // 0..3  -> h cols

    __shared__ __align__(16) float As[16][68];   // [e][r], padded
    __shared__ __align__(16) float Ws[16][68];   // [e][c], padded

    const int tid = threadIdx.x;
    const int tx = tid & 15;
    const int ty = tid >> 4;

    float c[4][4];
#pragma unroll
    for (int i = 0; i < 4; ++i)
#pragma unroll
        for (int j = 0; j < 4; ++j) c[i][j] = 0.0f;

    const int lr = tid >> 2;     // 0..63 loader row
    const int le = tid & 3;      // 0..3 loader e-quad

    for (int e0 = 0; e0 < EE; e0 += 16) {
        __syncthreads();
        {
            float4 va = *(const float4*)(A + (size_t)(row0 + lr) * EE + e0 + 4 * le);
            As[4 * le + 0][lr] = va.x;
            As[4 * le + 1][lr] = va.y;
            As[4 * le + 2][lr] = va.z;
            As[4 * le + 3][lr] = va.w;
            float4 vw = *(const float4*)(W + (size_t)(col0 + lr) * EE + e0 + 4 * le);
            Ws[4 * le + 0][lr] = vw.x;
            Ws[4 * le + 1][lr] = vw.y;
            Ws[4 * le + 2][lr] = vw.z;
            Ws[4 * le + 3][lr] = vw.w;
        }
        __syncthreads();
#pragma unroll
        for (int e = 0; e < 16; ++e) {
            float4 a4 = *(const float4*)(&As[e][4 * ty]);
            float4 w4 = *(const float4*)(&Ws[e][4 * tx]);
            float av[4] = {a4.x, a4.y, a4.z, a4.w};
            float wv[4] = {w4.x, w4.y, w4.z, w4.w};
#pragma unroll
            for (int i = 0; i < 4; ++i)
#pragma unroll
                for (int j = 0; j < 4; ++j)
                    c[i][j] = fmaf(av[i], wv[j], c[i][j]);
        }
    }

#pragma unroll
    for (int i = 0; i < 4; ++i) {
        float4 o = make_float4(c[i][0], c[i][1], c[i][2], c[i][3]);
        *(float4*)(C + (size_t)(row0 + 4 * ty + i) * HH + col0 + 4 * tx) = o;
    }
}

// ---------------------------------------------------------------------------
// Scores kernel: s[b,q,k] = sum_h w_v[h]*tanh(qp[b,q,h] + kp[b,k,h])
// Grid: 1024 blocks = b(4) x qtile(64, 8 queries) x ksplit(4, 128 keys).
// Block: 256 threads = 8 warps; warp w owns query qt*8+w.
// Lanes span h: lane holds q/w_v values for h in {4l..4l+3, 128+4l..128+4l+3}
// in registers. k rows staged in smem (32 keys x 256 h = 32 KB), read via
// conflict-free LDS.128. MUFU.TANH is the designed bottleneck.
// ---------------------------------------------------------------------------
__global__ __launch_bounds__(256) void scores_kernel(const float* __restrict__ w_v)
{
    __shared__ __align__(16) float kt[32 * HH];   // 32 KB

    const int tid  = threadIdx.x;
    const int w    = tid >> 5;
    const int lane = tid & 31;

    const int bx = blockIdx.x;
    const int b  = bx >> 8;
    const int qt = (bx >> 2) & 63;
    const int ks = bx & 3;
    const int qi = qt * 8 + w;

    const float* gq = (const float*)g_qv;
    const float* gk = (const float*)g_kv;
    float*       gs = (float*)g_sv;

    const float4* qrow = (const float4*)(gq + (size_t)(b * QQ + qi) * HH);
    const float4  qa = qrow[lane];
    const float4  qb = qrow[32 + lane];
    const float4* wv4 = (const float4*)w_v;
    const float4  wa = wv4[lane];
    const float4  wb = wv4[32 + lane];

    for (int t = 0; t < 4; ++t) {
        const int kbase = ks * 128 + t * 32;
        __syncthreads();
        {
            const float4* ksrc = (const float4*)(gk + (size_t)(b * KK + kbase) * HH);
            float4* kdst = (float4*)kt;
#pragma unroll
            for (int j = 0; j < 8; ++j)
                kdst[tid + j * 256] = ksrc[tid + j * 256];
        }
        __syncthreads();

        float* srow = gs + (size_t)(b * QQ + qi) * KK + kbase;

#pragma unroll 2
        for (int kk = 0; kk < 32; ++kk) {
            const float4* krow = (const float4*)(kt + kk * HH);
            const float4 ka = krow[lane];
            const float4 kb = krow[32 + lane];

            float a0 = wa.x * tanh_fast(qa.x + ka.x);
            float a1 = wa.y * tanh_fast(qa.y + ka.y);
            a0 = fmaf(wa.z, tanh_fast(qa.z + ka.z), a0);
            a1 = fmaf(wa.w, tanh_fast(qa.w + ka.w), a1);
            a0 = fmaf(wb.x, tanh_fast(qb.x + kb.x), a0);
            a1 = fmaf(wb.y, tanh_fast(qb.y + kb.y), a1);
            a0 = fmaf(wb.z, tanh_fast(qb.z + kb.z), a0);
            a1 = fmaf(wb.w, tanh_fast(qb.w + kb.w), a1);
            float acc = a0 + a1;

#pragma unroll
            for (int o = 16; o > 0; o >>= 1)
                acc += __shfl_xor_sync(0xffffffffu, acc, o);

            if (lane == 0) srow[kk] = acc;
        }
    }
}

// ---------------------------------------------------------------------------
// Softmax over K + attn @ V.
// Grid: 256 blocks = b(4) x qtile(64, 8 queries). Block: 256 threads.
// Phase 1: warp w softmaxes score row w (512 values) in smem.
// Phase 2: thread (qp = tid>>6, dq = tid&63) accumulates out[2 queries][4 dv]
//          as float4; V row loads are coalesced LDG.128, reused across 8 queries.
// ---------------------------------------------------------------------------
__global__ __launch_bounds__(256) void softmax_av_kernel(
    const float* __restrict__ values, float* __restrict__ out)
{
    __shared__ __align__(16) float p[8 * 512];   // 16 KB
    __shared__ float invs[8];

    const int bx = blockIdx.x;
    const int b  = bx >> 6;
    const int qt = bx & 63;
    const int tid = threadIdx.x;

    {
        const float4* src = (const float4*)((const float*)g_sv + (size_t)(b * QQ + qt * 8) * KK);
        float4* dst = (float4*)p;
#pragma unroll
        for (int j = 0; j < 4; ++j)
            dst[tid + j * 256] = src[tid + j * 256];
    }
    __syncthreads();

    {
        const int w = tid >> 5, lane = tid & 31;
        float* row = p + w * 512;
        float m = -1e30f;
#pragma unroll
        for (int j = 0; j < 16; ++j) m = fmaxf(m, row[lane + 32 * j]);
#pragma unroll
        for (int o = 16; o > 0; o >>= 1)
            m = fmaxf(m, __shfl_xor_sync(0xffffffffu, m, o));
        float sum = 0.0f;
#pragma unroll
        for (int j = 0; j < 16; ++j) {
            float e = __expf(row[lane + 32 * j] - m);
            row[lane + 32 * j] = e;
            sum += e;
        }
#pragma unroll
        for (int o = 16; o > 0; o >>= 1)
            sum += __shfl_xor_sync(0xffffffffu, sum, o);
        if (lane == 0) invs[w] = 1.0f / sum;
    }
    __syncthreads();

    const int dq = tid & 63;   // float4 column of DV
    const int qp = tid >> 6;   // 0..3 -> queries 2qp, 2qp+1
    const float* p0r = p + (2 * qp) * 512;
    const float* p1r = p + (2 * qp + 1) * 512;
    const float4* V = (const float4*)(values + (size_t)b * KK * DVV);

    float4 acc0 = make_float4(0.f, 0.f, 0.f, 0.f);
    float4 acc1 = make_float4(0.f, 0.f, 0.f, 0.f);

#pragma unroll 4
    for (int k = 0; k < KK; ++k) {
        const float4 v = V[k * (DVV / 4) + dq];
        const float a = p0r[k];
        const float c = p1r[k];
        acc0.x = fmaf(a, v.x, acc0.x);
        acc0.y = fmaf(a, v.y, acc0.y);
        acc0.z = fmaf(a, v.z, acc0.z);
        acc0.w = fmaf(a, v.w, acc0.w);
        acc1.x = fmaf(c, v.x, acc1.x);
        acc1.y = fmaf(c, v.y, acc1.y);
        acc1.z = fmaf(c, v.z, acc1.z);
        acc1.w = fmaf(c, v.w, acc1.w);
    }

    const float i0 = invs[2 * qp];
    const float i1 = invs[2 * qp + 1];
    acc0.x *= i0; acc0.y *= i0; acc0.z *= i0; acc0.w *= i0;
    acc1.x *= i1; acc1.y *= i1; acc1.z *= i1; acc1.w *= i1;

    const int q0 = qt * 8 + 2 * qp;
    *(float4*)(out + (size_t)(b * QQ + q0) * DVV + 4 * dq)       = acc0;
    *(float4*)(out + (size_t)(b * QQ + q0 + 1) * DVV + 4 * dq)   = acc1;
}

// ---------------------------------------------------------------------------
extern "C" void kernel_launch(void* const* d_in, const int* in_sizes, int n_in,
                              void* d_out, int out_size)
{
    const float* queries = (const float*)d_in[0];
    const float* keys    = (const float*)d_in[1];
    const float* values  = (const float*)d_in[2];
    const float* W_q     = (const float*)d_in[3];
    const float* W_k     = (const float*)d_in[4];
    const float* w_v     = (const float*)d_in[5];
    float* out = (float*)d_out;

    proj_kernel<<<dim3(32, 4, 2), 256>>>(queries, W_q, keys, W_k);
    scores_kernel<<<1024, 256>>>(w_v);
    softmax_av_kernel<<<256, 256>>>(values, out);
}